// round 17
// baseline (speedup 1.0000x reference)
#include <cuda_runtime.h>
#include <cuda_fp16.h>
#include <mma.h>
#include <math.h>

using namespace nvcuda;

#define NN 100000
#define EE 1600000
#define MM (EE + NN)
#define NT 391           // ceil(NN / 256) scan tiles
#define EPSV 1e-5f

// ---------------- scratch (static device allocations; no cudaMalloc) ----------------
__device__ int   g_is64 = 1;        // detection only ever clears -> stable across replays
__device__ int   g_deg[NN];
__device__ float g_dinv[NN];
__device__ int   g_start[NN];
__device__ int   g_cursor[NN];
__device__ unsigned long long g_scst[NT];   // decoupled-lookback state: (val<<2)|flag
__device__ int2  g_cw[MM];          // (src, norm-bits) per CSR slot
__device__ __align__(16) float g_h[NN * 64];      // fp16 rows, stride 64 halves (2x sized)
__device__ __align__(16) float g_agg[NN * 64];    // fp16 rows, stride 64 halves
__device__ float g_stats1[32 * 128];  // 32 contention buckets x [sum(64), sumsq(64)]
__device__ float g_stats2[32 * 128];
__device__ __align__(16) __half g_W1h[64 * 64];   // W1 in fp16
__device__ __align__(16) __half g_W2h[64 * 64];   // BN1-folded W2, fp16
__device__ __align__(16) __half g_W3h[64 * 64];   // BN2-folded W3, fp16, cols 40-63 = 0
__device__ float g_t2[64];
__device__ __align__(16) float g_t3[64];
__device__ __align__(16) float g_zero64[64];

__device__ __forceinline__ unsigned h2u(__half2 h) {
    return *reinterpret_cast<unsigned*>(&h);
}

// ---------------- graph init + sampled dtype detect + W1 fp16 convert ----------------
__global__ void k_init(const long long* __restrict__ p, const float* __restrict__ W1) {
    int i = blockIdx.x * blockDim.x + threadIdx.x;
    if (i < NN) g_deg[i] = 1;                        // self-loop
    if (i < 32 * 128) { g_stats1[i] = 0.f; g_stats2[i] = 0.f; }
    if (i < 64) g_zero64[i] = 0.f;
    if (i < NT) g_scst[i] = 0ull;                    // scan states reset each launch
    if (i < 64 * 64) g_W1h[i] = __float2half_rn(W1[i]);
    if (i < 8192) {
        long long v = p[(size_t)i * 195];            // max idx < EE int64 slots
        if (v < 0 || v >= NN) g_is64 = 0;            // only writes 0: race-free
    }
}

// ---------------- degree: 4 edges per thread ----------------
__global__ void k_degree(const void* __restrict__ ei) {
    int i = blockIdx.x * blockDim.x + threadIdx.x;
    if (i >= EE / 4) return;
    if (g_is64) {
        const longlong2* p = (const longlong2*)ei;
        longlong2 a = p[EE / 2 + i * 2];
        longlong2 b = p[EE / 2 + i * 2 + 1];
        if ((unsigned long long)a.x < NN) atomicAdd(&g_deg[(int)a.x], 1);
        if ((unsigned long long)a.y < NN) atomicAdd(&g_deg[(int)a.y], 1);
        if ((unsigned long long)b.x < NN) atomicAdd(&g_deg[(int)b.x], 1);
        if ((unsigned long long)b.y < NN) atomicAdd(&g_deg[(int)b.y], 1);
    } else {
        int4 v = ((const int4*)ei)[EE / 4 + i];
        if ((unsigned)v.x < NN) atomicAdd(&g_deg[v.x], 1);
        if ((unsigned)v.y < NN) atomicAdd(&g_deg[v.y], 1);
        if ((unsigned)v.z < NN) atomicAdd(&g_deg[v.z], 1);
        if ((unsigned)v.w < NN) atomicAdd(&g_deg[v.w], 1);
    }
}

// ---------------- single-pass scan: decoupled lookback + fused dinv ----------------
// flag 0 = not ready, 1 = aggregate published, 2 = inclusive prefix published.
// All NT=391 blocks are co-resident (100K threads << chip capacity): no deadlock.
__global__ void k_scan() {
    int tid = threadIdx.x;
    int lane = tid & 31, wrp = tid >> 5;
    int b = blockIdx.x;
    int idx = b * 256 + tid;
    int d = 0;
    if (idx < NN) {
        d = g_deg[idx];
        g_dinv[idx] = rsqrtf((float)d);
    }
    // warp inclusive scan
    int v = d;
    #pragma unroll
    for (int o = 1; o < 32; o <<= 1) {
        int u = __shfl_up_sync(0xffffffffu, v, o);
        if (lane >= o) v += u;
    }
    __shared__ int wsum[8];
    __shared__ int s_off;
    if (lane == 31) wsum[wrp] = v;
    __syncthreads();
    if (tid < 8) {                       // exclusive scan of 8 warp totals
        int x = wsum[tid];
        int y = x;
        #pragma unroll
        for (int o = 1; o < 8; o <<= 1) {
            int u = __shfl_up_sync(0xffu, y, o);
            if (tid >= o) y += u;
        }
        wsum[tid] = y - x;
        if (tid == 7) {
            int total = y;               // block total
            if (b == 0) {
                atomicExch(&g_scst[0], ((unsigned long long)total << 2) | 2ull);
                s_off = 0;
            } else {
                atomicExch(&g_scst[b], ((unsigned long long)total << 2) | 1ull);
                long long sum = 0;
                int j = b - 1;
                while (j >= 0) {
                    unsigned long long st;
                    do { st = atomicAdd(&g_scst[j], 0ull); } while ((st & 3ull) == 0ull);
                    sum += (long long)(st >> 2);
                    if ((st & 3ull) == 2ull) break;
                    j--;
                }
                atomicExch(&g_scst[b],
                           ((unsigned long long)(total + sum) << 2) | 2ull);
                s_off = (int)sum;
            }
        }
    }
    __syncthreads();
    if (idx < NN) {
        int p = s_off + wsum[wrp] + v - d;   // exclusive position
        g_start[idx] = p;
        g_cursor[idx] = p;
    }
}

// CSR fill; 4 edges per thread, self-loops appended. (row-sum computed in agg)
__device__ __forceinline__ void fill_one(int s, int d) {
    float w = g_dinv[s] * g_dinv[d];
    int pos = atomicAdd(&g_cursor[d], 1);
    g_cw[pos] = make_int2(s, __float_as_int(w));
}

__global__ void k_fill(const void* __restrict__ ei) {
    int i = blockIdx.x * blockDim.x + threadIdx.x;
    if (i < EE / 4) {
        if (g_is64) {
            const longlong2* p = (const longlong2*)ei;
            longlong2 sa = p[i * 2],           sb = p[i * 2 + 1];
            longlong2 da = p[EE / 2 + i * 2],  db = p[EE / 2 + i * 2 + 1];
            if ((unsigned long long)sa.x < NN && (unsigned long long)da.x < NN)
                fill_one((int)sa.x, (int)da.x);
            if ((unsigned long long)sa.y < NN && (unsigned long long)da.y < NN)
                fill_one((int)sa.y, (int)da.y);
            if ((unsigned long long)sb.x < NN && (unsigned long long)db.x < NN)
                fill_one((int)sb.x, (int)db.x);
            if ((unsigned long long)sb.y < NN && (unsigned long long)db.y < NN)
                fill_one((int)sb.y, (int)db.y);
        } else {
            int4 sv = ((const int4*)ei)[i];
            int4 dv = ((const int4*)ei)[EE / 4 + i];
            if ((unsigned)sv.x < NN && (unsigned)dv.x < NN) fill_one(sv.x, dv.x);
            if ((unsigned)sv.y < NN && (unsigned)dv.y < NN) fill_one(sv.y, dv.y);
            if ((unsigned)sv.z < NN && (unsigned)dv.z < NN) fill_one(sv.z, dv.z);
            if ((unsigned)sv.w < NN && (unsigned)dv.w < NN) fill_one(sv.w, dv.w);
        }
    } else {
        int n = i - EE / 4;
        if (n < NN) fill_one(n, n);        // self-loop
    }
}

// ---------------- tensor-core GEMM: out[N x 64](fp16) = in[N x 64] @ Wh[64 x 64] ----
template <bool HIN>
__global__ void __launch_bounds__(256)
k_gemm_tc(const void* __restrict__ in, const __half* __restrict__ Wh,
          __half* __restrict__ out) {
    __shared__ __half As[64 * 72];   // ldm 72 halves (144B rows, 16B-aligned)
    __shared__ __half Bs[64 * 72];
    int tid = threadIdx.x;
    int row0 = blockIdx.x * 64;

    for (int i = tid; i < 512; i += 256) {
        int k = i >> 3, c8 = i & 7;
        *(uint4*)&Bs[k * 72 + c8 * 8] = ((const uint4*)Wh)[i];
    }
    for (int i = tid; i < 512; i += 256) {
        int r = i >> 3, c8 = i & 7;
        int gr = row0 + r;
        uint4 v = make_uint4(0u, 0u, 0u, 0u);
        if (gr < NN) {
            if (HIN) {
                v = *(const uint4*)((const __half*)in + (size_t)gr * 64 + c8 * 8);
            } else {
                const float4* f4 = (const float4*)((const float*)in + (size_t)gr * 64 + c8 * 8);
                float4 f0 = f4[0], f1 = f4[1];
                v.x = h2u(__floats2half2_rn(f0.x, f0.y));
                v.y = h2u(__floats2half2_rn(f0.z, f0.w));
                v.z = h2u(__floats2half2_rn(f1.x, f1.y));
                v.w = h2u(__floats2half2_rn(f1.z, f1.w));
            }
        }
        *(uint4*)&As[r * 72 + c8 * 8] = v;
    }
    __syncthreads();

    int wid = tid >> 5;
    int wr = wid >> 1, wc = wid & 1;     // 4 row groups x 2 col groups (16x32 each)
    wmma::fragment<wmma::accumulator, 16, 16, 16, float> c0, c1;
    wmma::fill_fragment(c0, 0.f);
    wmma::fill_fragment(c1, 0.f);
    #pragma unroll
    for (int kk = 0; kk < 4; kk++) {
        wmma::fragment<wmma::matrix_a, 16, 16, 16, __half, wmma::row_major> a;
        wmma::load_matrix_sync(a, &As[wr * 16 * 72 + kk * 16], 72);
        wmma::fragment<wmma::matrix_b, 16, 16, 16, __half, wmma::row_major> b;
        wmma::load_matrix_sync(b, &Bs[kk * 16 * 72 + wc * 32], 72);
        wmma::mma_sync(c0, a, b, c0);
        wmma::load_matrix_sync(b, &Bs[kk * 16 * 72 + wc * 32 + 16], 72);
        wmma::mma_sync(c1, a, b, c1);
    }
    wmma::fragment<wmma::accumulator, 16, 16, 16, __half> h0, h1;
    #pragma unroll
    for (int i = 0; i < c0.num_elements; i++) {
        h0.x[i] = __float2half_rn(c0.x[i]);
        h1.x[i] = __float2half_rn(c1.x[i]);
    }
    __half* op = out + (size_t)(row0 + wr * 16) * 64 + wc * 32;
    wmma::store_matrix_sync(op, h0, 64, wmma::mem_row_major);
    wmma::store_matrix_sync(op + 16, h1, 64, wmma::mem_row_major);
}

// ---------------- aggregation (NC=64, fp16 h) + fused BN stats, fp16 output --------
__global__ void __launch_bounds__(256)
k_agg64h(const uint4* __restrict__ h4, const float* __restrict__ bias,
         const float* __restrict__ t, __half* __restrict__ out,
         float* __restrict__ st) {
    __shared__ float s_sum[8][64];
    __shared__ float s_sq[8][64];
    int tid = threadIdx.x;
    int wIdx = tid >> 5;
    int wid  = blockIdx.x * 8 + wIdx;      // always < NN
    int lane = tid & 31;
    int q = lane >> 3, ql = lane & 7;
    int stt = g_start[wid], en = stt + g_deg[wid];
    float acc[8];
    float accw = 0.f;                      // row-sum of norms
    #pragma unroll
    for (int i = 0; i < 8; i++) acc[i] = 0.f;

    #pragma unroll 4
    for (int e = stt + q; e < en; e += 4) {
        int2 c = __ldg(&g_cw[e]);
        uint4 v = __ldg(h4 + (size_t)c.x * 8 + ql);   // 8 halves of the row
        float w = __int_as_float(c.y);
        accw += w;
        float2 f;
        f = __half22float2(*(const __half2*)&v.x); acc[0] += w * f.x; acc[1] += w * f.y;
        f = __half22float2(*(const __half2*)&v.y); acc[2] += w * f.x; acc[3] += w * f.y;
        f = __half22float2(*(const __half2*)&v.z); acc[4] += w * f.x; acc[5] += w * f.y;
        f = __half22float2(*(const __half2*)&v.w); acc[6] += w * f.x; acc[7] += w * f.y;
    }
    #pragma unroll
    for (int i = 0; i < 8; i++) {
        acc[i] += __shfl_xor_sync(0xffffffffu, acc[i], 8);
        acc[i] += __shfl_xor_sync(0xffffffffu, acc[i], 16);
    }
    accw += __shfl_xor_sync(0xffffffffu, accw, 8);
    accw += __shfl_xor_sync(0xffffffffu, accw, 16);
    if (q == 0) {   // lanes 0-7 hold full sums for cols ql*8 .. ql*8+7
        float sd = accw;
        const float4* b4 = (const float4*)(bias + ql * 8);
        const float4* t4 = (const float4*)(t + ql * 8);
        float4 b0 = __ldg(b4), b1 = __ldg(b4 + 1);
        float4 t0 = __ldg(t4), t1 = __ldg(t4 + 1);
        float o[8];
        o[0] = acc[0] + b0.x + sd * t0.x;
        o[1] = acc[1] + b0.y + sd * t0.y;
        o[2] = acc[2] + b0.z + sd * t0.z;
        o[3] = acc[3] + b0.w + sd * t0.w;
        o[4] = acc[4] + b1.x + sd * t1.x;
        o[5] = acc[5] + b1.y + sd * t1.y;
        o[6] = acc[6] + b1.z + sd * t1.z;
        o[7] = acc[7] + b1.w + sd * t1.w;
        uint4 pk;
        pk.x = h2u(__floats2half2_rn(o[0], o[1]));
        pk.y = h2u(__floats2half2_rn(o[2], o[3]));
        pk.z = h2u(__floats2half2_rn(o[4], o[5]));
        pk.w = h2u(__floats2half2_rn(o[6], o[7]));
        *(uint4*)(out + (size_t)wid * 64 + ql * 8) = pk;
        #pragma unroll
        for (int i = 0; i < 8; i++) {
            s_sum[wIdx][ql * 8 + i] = o[i];
            s_sq [wIdx][ql * 8 + i] = o[i] * o[i];
        }
    }
    __syncthreads();
    if (tid < 64) {
        float a = 0.f, b = 0.f;
        #pragma unroll
        for (int w = 0; w < 8; w++) { a += s_sum[w][tid]; b += s_sq[w][tid]; }
        int bkt = (blockIdx.x & 31) * 128;
        atomicAdd(&st[bkt + tid], a);
        atomicAdd(&st[bkt + tid + 64], b);
    }
}

// ---------------- layer-3 aggregation (fp16 h, 40 valid cols of 64) + log_softmax ----
__global__ void k_agg40lsmh(const uint4* __restrict__ h4, const float* __restrict__ bias,
                            const float* __restrict__ t, float* __restrict__ emb,
                            float* __restrict__ out) {
    int wid  = (blockIdx.x * blockDim.x + threadIdx.x) >> 5;
    int lane = threadIdx.x & 31;
    if (wid >= NN) return;
    int q = lane >> 3, ql = lane & 7;
    int stt = g_start[wid], en = stt + g_deg[wid];
    float acc[8];
    float accw = 0.f;
    #pragma unroll
    for (int i = 0; i < 8; i++) acc[i] = 0.f;

    #pragma unroll 4
    for (int e = stt + q; e < en; e += 4) {
        int2 c = __ldg(&g_cw[e]);
        uint4 v = __ldg(h4 + (size_t)c.x * 8 + ql);
        float w = __int_as_float(c.y);
        accw += w;
        float2 f;
        f = __half22float2(*(const __half2*)&v.x); acc[0] += w * f.x; acc[1] += w * f.y;
        f = __half22float2(*(const __half2*)&v.y); acc[2] += w * f.x; acc[3] += w * f.y;
        f = __half22float2(*(const __half2*)&v.z); acc[4] += w * f.x; acc[5] += w * f.y;
        f = __half22float2(*(const __half2*)&v.w); acc[6] += w * f.x; acc[7] += w * f.y;
    }
    #pragma unroll
    for (int i = 0; i < 8; i++) {
        acc[i] += __shfl_xor_sync(0xffffffffu, acc[i], 8);
        acc[i] += __shfl_xor_sync(0xffffffffu, acc[i], 16);
    }
    accw += __shfl_xor_sync(0xffffffffu, accw, 8);
    accw += __shfl_xor_sync(0xffffffffu, accw, 16);

    bool fin = (q == 0) && (ql < 5);       // lanes 0-4 hold cols ql*8..ql*8+7 (40 total)
    float o[8];
    if (fin) {
        float sd = accw;
        const float4* b4 = (const float4*)(bias + ql * 8);
        const float4* t4 = (const float4*)(t + ql * 8);
        float4 b0 = __ldg(b4), b1 = __ldg(b4 + 1);
        float4 t0 = __ldg(t4), t1 = __ldg(t4 + 1);
        o[0] = acc[0] + b0.x + sd * t0.x;
        o[1] = acc[1] + b0.y + sd * t0.y;
        o[2] = acc[2] + b0.z + sd * t0.z;
        o[3] = acc[3] + b0.w + sd * t0.w;
        o[4] = acc[4] + b1.x + sd * t1.x;
        o[5] = acc[5] + b1.y + sd * t1.y;
        o[6] = acc[6] + b1.z + sd * t1.z;
        o[7] = acc[7] + b1.w + sd * t1.w;
        float4* ep = (float4*)(emb + (size_t)wid * 40 + ql * 8);
        ep[0] = make_float4(o[0], o[1], o[2], o[3]);
        ep[1] = make_float4(o[4], o[5], o[6], o[7]);
    }
    float m = -3.4e38f;
    if (fin) {
        #pragma unroll
        for (int i = 0; i < 8; i++) m = fmaxf(m, o[i]);
    }
    #pragma unroll
    for (int od = 16; od > 0; od >>= 1) m = fmaxf(m, __shfl_xor_sync(0xffffffffu, m, od));
    float s = 0.f;
    if (fin) {
        #pragma unroll
        for (int i = 0; i < 8; i++) s += __expf(o[i] - m);
    }
    #pragma unroll
    for (int od = 16; od > 0; od >>= 1) s += __shfl_xor_sync(0xffffffffu, s, od);
    float lse = m + logf(s);
    if (fin) {
        float4* op = (float4*)(out + (size_t)wid * 40 + ql * 8);
        op[0] = make_float4(o[0] - lse, o[1] - lse, o[2] - lse, o[3] - lse);
        op[1] = make_float4(o[4] - lse, o[5] - lse, o[6] - lse, o[7] - lse);
    }
}

// ---------------- fold BN into next layer's weights -> fp16 Wf (zero-padded) --------
template <int NCN>
__global__ void k_fold(const float* __restrict__ W, const float* __restrict__ g,
                       const float* __restrict__ be, const float* __restrict__ st,
                       __half* __restrict__ Wf, float* __restrict__ t) {
    __shared__ float a[64], c[64];
    int tid = threadIdx.x;
    __shared__ float red[128];
    if (tid < 128) {
        float v = 0.f;
        #pragma unroll 8
        for (int b = 0; b < 32; b++) v += st[b * 128 + tid];
        red[tid] = v;
    }
    __syncthreads();
    if (tid < 64) {
        float mean = red[tid] * (1.f / NN);
        float var  = red[tid + 64] * (1.f / NN) - mean * mean;
        float ai = g[tid] * rsqrtf(var + EPSV);
        a[tid] = ai;
        c[tid] = be[tid] - mean * ai;
    }
    __syncthreads();
    for (int i = tid; i < 64 * 64; i += 256) {
        int k = i >> 6, j = i & 63;
        float v = (j < NCN) ? a[k] * W[k * NCN + j] : 0.f;
        Wf[i] = __float2half_rn(v);
    }
    if (tid < NCN) {
        float tv = 0.f;
        #pragma unroll
        for (int k = 0; k < 64; k++) tv += c[k] * W[k * NCN + tid];
        t[tid] = tv;
    }
}

// ---------------- launcher ----------------
extern "C" void kernel_launch(void* const* d_in, const int* in_sizes, int n_in,
                              void* d_out, int out_size) {
    const float* x   = (const float*)d_in[0];
    const void*  ei  = d_in[1];                 // int32 or int64, detected on device
    const float* W1  = (const float*)d_in[2];
    const float* b1  = (const float*)d_in[3];
    const float* W2  = (const float*)d_in[4];
    const float* b2  = (const float*)d_in[5];
    const float* W3  = (const float*)d_in[6];
    const float* b3  = (const float*)d_in[7];
    const float* g1  = (const float*)d_in[8];
    const float* be1 = (const float*)d_in[9];
    const float* g2  = (const float*)d_in[10];
    const float* be2 = (const float*)d_in[11];
    float* out = (float*)d_out;

    float *hP, *aP, *t2P, *t3P, *z64P, *s1P, *s2P;
    __half *W1hP, *W2hP, *W3hP;
    cudaGetSymbolAddress((void**)&hP,   g_h);
    cudaGetSymbolAddress((void**)&aP,   g_agg);
    cudaGetSymbolAddress((void**)&W1hP, g_W1h);
    cudaGetSymbolAddress((void**)&W2hP, g_W2h);
    cudaGetSymbolAddress((void**)&W3hP, g_W3h);
    cudaGetSymbolAddress((void**)&t2P,  g_t2);
    cudaGetSymbolAddress((void**)&t3P,  g_t3);
    cudaGetSymbolAddress((void**)&z64P, g_zero64);
    cudaGetSymbolAddress((void**)&s1P,  g_stats1);
    cudaGetSymbolAddress((void**)&s2P,  g_stats2);

    // output layout: (out, emb) concatenated
    float* emb = (out_size >= 2 * NN * 40) ? (out + NN * 40) : aP;

    // graph build (single stream)
    k_init  <<<NT, 256>>>((const long long*)ei, W1);
    k_degree<<<(EE / 4 + 255) / 256, 256>>>(ei);
    k_scan  <<<NT, 256>>>();
    k_fill  <<<(EE / 4 + NN + 255) / 256, 256>>>(ei);

    // layer 1 (tensor-core GEMM, h fp16, agg out fp16, stats fused)
    k_gemm_tc<false><<<(NN + 63) / 64, 256>>>(x, W1hP, (__half*)hP);
    k_agg64h  <<<NN / 8, 256>>>((const uint4*)hP, b1, z64P, (__half*)aP, s1P);
    k_fold<64><<<1, 256>>>(W2, g1, be1, s1P, W2hP, t2P);

    // layer 2 (BN1 folded into W2h; fp16 throughout, stats fused)
    k_gemm_tc<true><<<(NN + 63) / 64, 256>>>(aP, W2hP, (__half*)hP);
    k_agg64h  <<<NN / 8, 256>>>((const uint4*)hP, b2, t2P, (__half*)aP, s2P);
    k_fold<40><<<1, 256>>>(W3, g2, be2, s2P, W3hP, t3P);

    // layer 3 (BN2 folded into W3h, zero-padded to 64 cols; fp16 h)
    // -> quarter-warp fp16 agg + fused log_softmax -> emb, out
    k_gemm_tc<true><<<(NN + 63) / 64, 256>>>(aP, W3hP, (__half*)hP);
    k_agg40lsmh<<<(NN + 7) / 8, 256>>>((const uint4*)hP, b3, t3P, emb, out);
}